// round 13
// baseline (speedup 1.0000x reference)
#include <cuda_runtime.h>
#include <cuda_bf16.h>
#include <mma.h>
#include <cstdint>

using namespace nvcuda;

#define B_     128
#define L_     128
#define D_     512
#define C_     512
#define NODES_ 255
#define NLEAF  (B_ * L_)        // 16384
#define NINT   (B_ * (L_ - 1)) // 16256
#define W0_    0.01227184630308513f   // 2*pi/512

// Static device scratch (bf16 everywhere except output).
__device__ __nv_bfloat16 g_lbf[(size_t)NLEAF * D_];  // leaf vectors
__device__ __nv_bfloat16 g_wbf[(size_t)C_ * D_];     // lin_w bf16
__device__ __nv_bfloat16 g_Wf [(size_t)D_ * D_];     // fwd DFT  [col][d]
__device__ __nv_bfloat16 g_WiT[(size_t)D_ * D_];     // inv DFT transposed [kf][n]
__device__ __nv_bfloat16 g_Wc [(size_t)C_ * D_];     // lin_w @ WiT  [c][kf]
__device__ __nv_bfloat16 g_F  [(size_t)NLEAF * D_];  // leaf spectra [Re0..256|Im1..255]
__device__ __nv_bfloat16 g_P  [(size_t)NINT * D_];   // conj(Fa)*Fb packed

// ---------------------------------------------------------------------------
// Small prep kernels
// ---------------------------------------------------------------------------
__global__ void k_embed(const int* __restrict__ ids, const float* __restrict__ emb) {
    int bl = blockIdx.x;
    int t  = threadIdx.x;
    int id = ids[bl];
    float4 v = reinterpret_cast<const float4*>(emb + (size_t)id * D_)[t];
    __nv_bfloat162 p0 = __floats2bfloat162_rn(v.x, v.y);
    __nv_bfloat162 p1 = __floats2bfloat162_rn(v.z, v.w);
    uint2 pk;
    pk.x = *reinterpret_cast<unsigned*>(&p0);
    pk.y = *reinterpret_cast<unsigned*>(&p1);
    reinterpret_cast<uint2*>(g_lbf + (size_t)bl * D_)[t] = pk;
}

__global__ void k_cvt_w(const float* __restrict__ w) {
    int i = blockIdx.x * blockDim.x + threadIdx.x;
    float4 v = reinterpret_cast<const float4*>(w)[i];
    __nv_bfloat162 p0 = __floats2bfloat162_rn(v.x, v.y);
    __nv_bfloat162 p1 = __floats2bfloat162_rn(v.z, v.w);
    uint2 pk;
    pk.x = *reinterpret_cast<unsigned*>(&p0);
    pk.y = *reinterpret_cast<unsigned*>(&p1);
    reinterpret_cast<uint2*>(g_wbf)[i] = pk;
}

// Wf[col][d]: col<=256 -> cos(2pi*col*d/512); col>=257 -> -sin(2pi*(col-256)*d/512)
__global__ void k_gen_wf() {
    int i = blockIdx.x * 256 + threadIdx.x;
    int col = i >> 9, d = i & 511;
    float v;
    if (col < 257) { int t = (col * d) & 511; v = cosf(t * W0_); }
    else           { int t = ((col - 256) * d) & 511; v = -sinf(t * W0_); }
    g_Wf[i] = __float2bfloat16(v);
}

// WiT[kf][n]: kf<=256 (k=kf): sc*cos(2pi*k*n/512); kf>=257: -(2/512)*sin(2pi*(kf-256)*n/512)
__global__ void k_gen_wit() {
    int i = blockIdx.x * 256 + threadIdx.x;
    int kf = i >> 9, n = i & 511;
    float v;
    if (kf < 257) {
        float sc = (kf == 0 || kf == 256) ? (1.0f / 512.0f) : (2.0f / 512.0f);
        int t = (kf * n) & 511;
        v = sc * cosf(t * W0_);
    } else {
        int t = ((kf - 256) * n) & 511;
        v = -(2.0f / 512.0f) * sinf(t * W0_);
    }
    g_WiT[i] = __float2bfloat16(v);
}

// ---------------------------------------------------------------------------
// Pointwise P = conj(Fa)*Fb, packed layout [Re0..Re256 | Im1..Im255].
// ---------------------------------------------------------------------------
__device__ __forceinline__ void unpack8(uint4 u, float* f) {
    __nv_bfloat162* h = reinterpret_cast<__nv_bfloat162*>(&u);
#pragma unroll
    for (int q = 0; q < 4; q++) {
        float2 t = __bfloat1622float2(h[q]);
        f[2 * q] = t.x; f[2 * q + 1] = t.y;
    }
}
__device__ __forceinline__ uint4 pack8(const float* f) {
    uint4 u;
    __nv_bfloat162 h0 = __floats2bfloat162_rn(f[0], f[1]);
    __nv_bfloat162 h1 = __floats2bfloat162_rn(f[2], f[3]);
    __nv_bfloat162 h2 = __floats2bfloat162_rn(f[4], f[5]);
    __nv_bfloat162 h3 = __floats2bfloat162_rn(f[6], f[7]);
    u.x = *reinterpret_cast<unsigned*>(&h0);
    u.y = *reinterpret_cast<unsigned*>(&h1);
    u.z = *reinterpret_cast<unsigned*>(&h2);
    u.w = *reinterpret_cast<unsigned*>(&h3);
    return u;
}

__global__ __launch_bounds__(128) void k_pw(const int* __restrict__ comp) {
    int node = blockIdx.x * 4 + (threadIdx.x >> 5);
    int lane = threadIdx.x & 31;
    int b    = node / 127;
    int li   = comp[2 * node];
    int ri   = comp[2 * node + 1];

    const __nv_bfloat16* Fa = g_F + (size_t)(b * 128 + li) * D_;
    const __nv_bfloat16* Fb = g_F + (size_t)(b * 128 + ri) * D_;
    __nv_bfloat16*       P  = g_P + (size_t)node * D_;

    int c = 8 * lane;
    float ar[8], ai[8], br[8], bi[8];
    unpack8(*reinterpret_cast<const uint4*>(Fa + c),       ar);
    unpack8(*reinterpret_cast<const uint4*>(Fa + 256 + c), ai);
    unpack8(*reinterpret_cast<const uint4*>(Fb + c),       br);
    unpack8(*reinterpret_cast<const uint4*>(Fb + 256 + c), bi);

    float re256a = ai[0], re256b = bi[0];
    if (lane == 0) { ai[0] = 0.0f; bi[0] = 0.0f; }

    float pr[8], pi[8];
#pragma unroll
    for (int q = 0; q < 8; q++) {
        pr[q] = fmaf(ar[q], br[q],  ai[q] * bi[q]);
        pi[q] = fmaf(ar[q], bi[q], -ai[q] * br[q]);
    }
    if (lane == 0) pi[0] = re256a * re256b;

    *reinterpret_cast<uint4*>(P + c)       = pack8(pr);
    *reinterpret_cast<uint4*>(P + 256 + c) = pack8(pi);
}

// ===========================================================================
// cp.async 4-stage pipelined WMMA GEMM, 64x64 warp tiles.
// C[128x128] = A[128x512] * B[128x512]^T, bf16 x bf16 -> fp32.
// 128 threads = 4 warps in 2x2 grid; warp tile 64x64 (4x4 frags).
// Per ks-slice: 8 fragment loads -> 16 mma_sync (ratio 0.5, 4x frag reuse).
// MODE 0: bf16 rows to outp (ld 512)
// MODE 2: bias+sigmoid, scatter internal-node rows
// MODE 3: bias+sigmoid, scatter leaf rows
// ===========================================================================
#define SK        40                 // smem row stride (bf16): 80B, 16B-multiple
#define STG       4
#define STAGE_EL  (128 * SK)         // elements per stage per matrix
#define STAGE_BY  (STAGE_EL * 2)     // bytes per stage per matrix
#define SMEMB     (STG * STAGE_BY * 2)   // 81920 bytes

__device__ __forceinline__ uint32_t smem_u32(const void* p) {
    return (uint32_t)__cvta_generic_to_shared(p);
}
__device__ __forceinline__ void cp16(uint32_t dst, const void* src) {
    asm volatile("cp.async.cg.shared.global [%0], [%1], 16;" :: "r"(dst), "l"(src));
}

template <int MODE>
__global__ __launch_bounds__(128) void k_gemm(const __nv_bfloat16* __restrict__ A,
                                              const __nv_bfloat16* __restrict__ Bm,
                                              const float* __restrict__ lb,
                                              void* __restrict__ outp) {
    extern __shared__ __nv_bfloat16 dsm[];
    __nv_bfloat16* sA = dsm;                      // [STG][128*SK]
    __nv_bfloat16* sB = dsm + STG * STAGE_EL;

    int tid  = threadIdx.x;        // 0..127
    int warp = tid >> 5;
    int lane = tid & 31;
    int wm   = warp & 1;           // 0..1 (M, 64 rows)
    int wn   = warp >> 1;          // 0..1 (N, 64 cols)
    int m0   = blockIdx.y * 128;
    int n0   = blockIdx.x * 128;

    // staging: thread tid owns row tid of A and of B; 4 x 16B chunks each.
    const __nv_bfloat16* gA = A  + (size_t)(m0 + tid) * D_;
    const __nv_bfloat16* gB = Bm + (size_t)(n0 + tid) * D_;
    uint32_t dA = smem_u32(sA + tid * SK);
    uint32_t dB = smem_u32(sB + tid * SK);

#define PF(s, kt)                                                             \
    do {                                                                      \
        _Pragma("unroll")                                                     \
        for (int c = 0; c < 4; c++) {                                         \
            cp16(dA + (s) * STAGE_BY + c * 16, gA + (kt) * 32 + c * 8);       \
            cp16(dB + (s) * STAGE_BY + c * 16, gB + (kt) * 32 + c * 8);       \
        }                                                                     \
    } while (0)

    wmma::fragment<wmma::accumulator, 16, 16, 16, float> acc[4][4];
#pragma unroll
    for (int mi = 0; mi < 4; mi++)
#pragma unroll
        for (int ni = 0; ni < 4; ni++)
            wmma::fill_fragment(acc[mi][ni], 0.0f);

    PF(0, 0); asm volatile("cp.async.commit_group;");
    PF(1, 1); asm volatile("cp.async.commit_group;");
    PF(2, 2); asm volatile("cp.async.commit_group;");

    for (int kt = 0; kt < 16; kt++) {
        asm volatile("cp.async.wait_group 2;");
        __syncthreads();
        if (kt + 3 < 16) PF((kt + 3) & 3, kt + 3);
        asm volatile("cp.async.commit_group;");

        int cur = kt & 3;
        const __nv_bfloat16* cA = sA + cur * STAGE_EL;
        const __nv_bfloat16* cB = sB + cur * STAGE_EL;
#pragma unroll
        for (int ks = 0; ks < 2; ks++) {
            wmma::fragment<wmma::matrix_a, 16, 16, 16, __nv_bfloat16, wmma::row_major> af[4];
            wmma::fragment<wmma::matrix_b, 16, 16, 16, __nv_bfloat16, wmma::col_major> bf[4];
#pragma unroll
            for (int mi = 0; mi < 4; mi++)
                wmma::load_matrix_sync(af[mi], &cA[(wm * 64 + mi * 16) * SK + ks * 16], SK);
#pragma unroll
            for (int ni = 0; ni < 4; ni++)
                wmma::load_matrix_sync(bf[ni], &cB[(wn * 64 + ni * 16) * SK + ks * 16], SK);
#pragma unroll
            for (int mi = 0; mi < 4; mi++)
#pragma unroll
                for (int ni = 0; ni < 4; ni++)
                    wmma::mma_sync(acc[mi][ni], af[mi], bf[ni], acc[mi][ni]);
        }
        __syncthreads();
    }
#undef PF

    // Epilogue: per-warp 16x20 fp32 bounce in (now free) stage smem.
    float* Csw = reinterpret_cast<float*>(dsm) + warp * 320;
    int er = lane >> 1;
    int ec = (lane & 1) * 8;
#pragma unroll
    for (int mi = 0; mi < 4; mi++) {
#pragma unroll
        for (int ni = 0; ni < 4; ni++) {
            __syncwarp();
            wmma::store_matrix_sync(Csw, acc[mi][ni], 20, wmma::mem_row_major);
            __syncwarp();
            int gn = n0 + wn * 64 + ni * 16 + ec;
            int gm = m0 + wm * 64 + mi * 16 + er;
            if (MODE == 0) {
                __nv_bfloat162 p0 = __floats2bfloat162_rn(Csw[er * 20 + ec + 0], Csw[er * 20 + ec + 1]);
                __nv_bfloat162 p1 = __floats2bfloat162_rn(Csw[er * 20 + ec + 2], Csw[er * 20 + ec + 3]);
                __nv_bfloat162 p2 = __floats2bfloat162_rn(Csw[er * 20 + ec + 4], Csw[er * 20 + ec + 5]);
                __nv_bfloat162 p3 = __floats2bfloat162_rn(Csw[er * 20 + ec + 6], Csw[er * 20 + ec + 7]);
                uint4 pk;
                pk.x = *reinterpret_cast<unsigned*>(&p0);
                pk.y = *reinterpret_cast<unsigned*>(&p1);
                pk.z = *reinterpret_cast<unsigned*>(&p2);
                pk.w = *reinterpret_cast<unsigned*>(&p3);
                *reinterpret_cast<uint4*>(
                    reinterpret_cast<__nv_bfloat16*>(outp) + (size_t)gm * D_ + gn) = pk;
            } else {
                int orow;
                if (MODE == 2) {
                    int bb = gm / 127;
                    int ss = gm - bb * 127;
                    orow = bb * NODES_ + L_ + ss;
                } else {
                    orow = (gm >> 7) * NODES_ + (gm & 127);
                }
                float4 b0 = *reinterpret_cast<const float4*>(&lb[gn]);
                float4 b1 = *reinterpret_cast<const float4*>(&lb[gn + 4]);
                float o[8];
#pragma unroll
                for (int j = 0; j < 8; j++) o[j] = Csw[er * 20 + ec + j];
                o[0] += b0.x; o[1] += b0.y; o[2] += b0.z; o[3] += b0.w;
                o[4] += b1.x; o[5] += b1.y; o[6] += b1.z; o[7] += b1.w;
#pragma unroll
                for (int j = 0; j < 8; j++) o[j] = 1.0f / (1.0f + __expf(-o[j]));
                float* op = reinterpret_cast<float*>(outp) + (size_t)orow * C_ + gn;
                *reinterpret_cast<float4*>(op)     = make_float4(o[0], o[1], o[2], o[3]);
                *reinterpret_cast<float4*>(op + 4) = make_float4(o[4], o[5], o[6], o[7]);
            }
        }
    }
}

// ---------------------------------------------------------------------------
// Launch
// ---------------------------------------------------------------------------
extern "C" void kernel_launch(void* const* d_in, const int* in_sizes, int n_in,
                              void* d_out, int out_size) {
    const int*   ids  = nullptr;
    const int*   comp = nullptr;
    const float* emb  = nullptr;
    const float* lw   = nullptr;
    const float* lb   = nullptr;

    for (int i = 0; i < n_in; i++) {
        switch (in_sizes[i]) {
            case 16384:    ids  = (const int*)d_in[i];   break;  // leaf_content_id [B,L]
            case 32512:    comp = (const int*)d_in[i];   break;  // composition_info [B,127,2]
            case 25600000: emb  = (const float*)d_in[i]; break;  // emb_weight [V,D]
            case 262144:   lw   = (const float*)d_in[i]; break;  // lin_w [C,D]
            case 512:      lb   = (const float*)d_in[i]; break;  // lin_b [C]
            default: break;                                       // content_mask (unused)
        }
    }

    float* out = (float*)d_out;

    // device-symbol addresses (host side; not stream ops -> capture-safe)
    __nv_bfloat16 *p_lbf, *p_wbf, *p_Wf, *p_WiT, *p_Wc, *p_F, *p_P;
    cudaGetSymbolAddress((void**)&p_lbf, g_lbf);
    cudaGetSymbolAddress((void**)&p_wbf, g_wbf);
    cudaGetSymbolAddress((void**)&p_Wf,  g_Wf);
    cudaGetSymbolAddress((void**)&p_WiT, g_WiT);
    cudaGetSymbolAddress((void**)&p_Wc,  g_Wc);
    cudaGetSymbolAddress((void**)&p_F,   g_F);
    cudaGetSymbolAddress((void**)&p_P,   g_P);

    // opt-in to 80KB dynamic smem (attribute set: not a stream op, capture-safe)
    static bool attr_done = false;
    if (!attr_done) {
        cudaFuncSetAttribute(k_gemm<0>, cudaFuncAttributeMaxDynamicSharedMemorySize, SMEMB);
        cudaFuncSetAttribute(k_gemm<2>, cudaFuncAttributeMaxDynamicSharedMemorySize, SMEMB);
        cudaFuncSetAttribute(k_gemm<3>, cudaFuncAttributeMaxDynamicSharedMemorySize, SMEMB);
        attr_done = true;
    }

    k_embed  <<<NLEAF, 128>>>(ids, emb);
    k_cvt_w  <<<256, 256>>>(lw);
    k_gen_wf <<<(D_ * D_) / 256, 256>>>();
    k_gen_wit<<<(D_ * D_) / 256, 256>>>();

    k_gemm<0><<<dim3(4, 4),           128, SMEMB>>>(p_wbf, p_WiT, lb, (void*)p_Wc);  // Wc
    k_gemm<0><<<dim3(4, NLEAF / 128), 128, SMEMB>>>(p_lbf, p_Wf,  lb, (void*)p_F);   // fwd FFT
    k_pw     <<<NINT / 4, 128>>>(comp);
    k_gemm<2><<<dim3(4, NINT / 128),  128, SMEMB>>>(p_P,   p_Wc,  lb, (void*)out);   // inv+logits
    k_gemm<3><<<dim3(4, NLEAF / 128), 128, SMEMB>>>(p_lbf, p_wbf, lb, (void*)out);   // leaf logits
}